// round 1
// baseline (speedup 1.0000x reference)
#include <cuda_runtime.h>

#define N_NODESC 100000
#define N_EDGESC 3200000
#define N_GRAPHSC 1024
#define HIDC 64
#define NCLS 21

// ---------------- scratch (device globals; no allocation) ----------------
__device__ float2 g_sc[N_NODESC];                 // {sum x[src], degree} per dst
__device__ float4 g_h1[N_NODESC * 16];            // h1 [N][64] node-major
__device__ float2 g_a2[32 * N_NODESC];            // agg2 pair-major: [pair p][node n]
__device__ float4 g_pooled[N_GRAPHSC * 16];       // pooled [G][64]
__device__ float  g_gcnt[N_GRAPHSC];
__device__ int    g_e32, g_b32;                   // 1 => indices are int32

// ---------------- zero scratch ----------------
__global__ void k_zero() {
    long i = (long)blockIdx.x * blockDim.x + threadIdx.x;
    long stride = (long)gridDim.x * blockDim.x;
    for (long j = i; j < 32L * N_NODESC; j += stride) g_a2[j] = make_float2(0.f, 0.f);
    for (long j = i; j < N_NODESC; j += stride) g_sc[j] = make_float2(0.f, 0.f);
    for (long j = i; j < N_GRAPHSC * 16; j += stride) g_pooled[j] = make_float4(0.f, 0.f, 0.f, 0.f);
    for (long j = i; j < N_GRAPHSC; j += stride) g_gcnt[j] = 0.f;
    if (i == 0) { g_e32 = 0; g_b32 = 0; }
}

// ---------------- dtype detection (int64 vs int32 indices) ----------------
// If data is int64 with values < 2^31, every odd 32-bit word is 0.
__global__ void k_detect(const int* ei, const int* bi) {
    int t = threadIdx.x;
    int accE = 0, accB = 0;
    for (int j = t; j < 8192; j += 256) accE |= ei[2 * j + 1];
    for (int j = t; j < 2048; j += 256) accB |= bi[2 * j + 1];
    for (int o = 16; o > 0; o >>= 1) {
        accE |= __shfl_xor_sync(0xffffffffu, accE, o);
        accB |= __shfl_xor_sync(0xffffffffu, accB, o);
    }
    if ((t & 31) == 0) {
        if (accE) atomicOr(&g_e32, 1);
        if (accB) atomicOr(&g_b32, 1);
    }
}

__device__ __forceinline__ int load_idx(const void* p, long i, bool is32) {
    if (is32) return ((const int*)p)[i];
    return (int)((const long long*)p)[i];
}

// ---------------- pass A: scalar aggregation for layer 1 ----------------
__global__ void k_edge_scalar(const void* eptr, const float* __restrict__ x) {
    bool e32 = (g_e32 != 0);
    long e = (long)blockIdx.x * blockDim.x + threadIdx.x;
    if (e >= N_EDGESC) return;
    int s = load_idx(eptr, e, e32);
    int d = load_idx(eptr, N_EDGESC + e, e32);
    atomicAdd(&g_sc[d], make_float2(x[s], 1.0f));   // vector RED (sm_90+)
}

// ---------------- pass B: materialize h1, count nodes per graph ----------------
__global__ void k_h1(const float* __restrict__ x, const void* bptr,
                     const float* __restrict__ W1l, const float* __restrict__ b1,
                     const float* __restrict__ W1r) {
    int idx = blockIdx.x * blockDim.x + threadIdx.x;   // [0, N*16)
    if (idx >= N_NODESC * 16) return;
    int n = idx >> 4, q = idx & 15;
    float2 sc = g_sc[n];
    float a1 = sc.x / fmaxf(sc.y, 1.0f);
    float xv = x[n];
    float4 wl = __ldg((const float4*)(W1l + 4 * q));
    float4 wr = __ldg((const float4*)(W1r + 4 * q));
    float4 bb = __ldg((const float4*)(b1 + 4 * q));
    float4 h;
    h.x = fmaxf(a1 * wl.x + xv * wr.x + bb.x, 0.f);
    h.y = fmaxf(a1 * wl.y + xv * wr.y + bb.y, 0.f);
    h.z = fmaxf(a1 * wl.z + xv * wr.z + bb.z, 0.f);
    h.w = fmaxf(a1 * wl.w + xv * wr.w + bb.w, 0.f);
    g_h1[n * 16 + q] = h;
    if (q == 0) {
        int g = load_idx(bptr, n, g_b32 != 0);
        atomicAdd(&g_gcnt[g], 1.0f);
    }
}

// ---------------- pass C: feature aggregation for layer 2 (dominant) ----------------
// Warp handles 32 edges: each lane loads one edge's (src,dst), then all lanes
// cooperatively process each edge: lane l moves feature pair 2l..2l+1.
__global__ void k_edge_feat(const void* eptr) {
    bool e32 = (g_e32 != 0);
    int warp = (blockIdx.x * blockDim.x + threadIdx.x) >> 5;   // 0..99999
    int lane = threadIdx.x & 31;
    long base = (long)warp * 32;
    int s = load_idx(eptr, base + lane, e32);
    int d = load_idx(eptr, N_EDGESC + base + lane, e32);
    const float2* __restrict__ h1v = (const float2*)g_h1;
    float2* __restrict__ a2row = g_a2 + (long)lane * N_NODESC;
#pragma unroll 8
    for (int j = 0; j < 32; j++) {
        int ss = __shfl_sync(0xffffffffu, s, j);
        int dd = __shfl_sync(0xffffffffu, d, j);
        float2 v = h1v[ss * 32 + lane];
        atomicAdd(&a2row[dd], v);                    // vector RED (sm_90+)
    }
}

// ---------------- pass D: layer-2 dense + relu + graph pooling ----------------
__global__ void __launch_bounds__(160) k_h2pool(
        const float* __restrict__ x, const void* bptr,
        const float* __restrict__ W1l, const float* __restrict__ b1, const float* __restrict__ W1r,
        const float* __restrict__ W2l, const float* __restrict__ b2, const float* __restrict__ W2r) {
    __shared__ float sWl[HIDC * HIDC];
    __shared__ float sWr[HIDC * HIDC];
    __shared__ float sW1[3][HIDC];
    int tid = threadIdx.x;
    for (int i = tid; i < HIDC * HIDC; i += 160) { sWl[i] = W2l[i]; sWr[i] = W2r[i]; }
    if (tid < HIDC) { sW1[0][tid] = W1l[tid]; sW1[1][tid] = W1r[tid]; sW1[2][tid] = b1[tid]; }
    __syncthreads();

    int n = blockIdx.x * 160 + tid;                  // exact: 625*160 = 100000
    float2 sc = g_sc[n];
    float inv1 = 1.0f / fmaxf(sc.y, 1.0f);
    float a1 = sc.x * inv1;
    float xv = x[n];
    int g = load_idx(bptr, n, g_b32 != 0);

    float4 acc[16];
#pragma unroll
    for (int jb = 0; jb < 16; jb++) acc[jb] = __ldg((const float4*)(b2 + 4 * jb));

#pragma unroll 1
    for (int p = 0; p < 32; p++) {
        float2 a2v = g_a2[(long)p * N_NODESC + n];
        float a2x = a2v.x * inv1, a2y = a2v.y * inv1;
        int k0 = 2 * p, k1 = 2 * p + 1;
        float h1a = fmaxf(a1 * sW1[0][k0] + xv * sW1[1][k0] + sW1[2][k0], 0.f);
        float h1b = fmaxf(a1 * sW1[0][k1] + xv * sW1[1][k1] + sW1[2][k1], 0.f);
        const float4* wl0 = (const float4*)(sWl + k0 * HIDC);
        const float4* wl1 = (const float4*)(sWl + k1 * HIDC);
        const float4* wr0 = (const float4*)(sWr + k0 * HIDC);
        const float4* wr1 = (const float4*)(sWr + k1 * HIDC);
#pragma unroll
        for (int jb = 0; jb < 16; jb++) {
            float4 w0 = wl0[jb], w1 = wl1[jb], u0 = wr0[jb], u1 = wr1[jb];
            acc[jb].x += a2x * w0.x + a2y * w1.x + h1a * u0.x + h1b * u1.x;
            acc[jb].y += a2x * w0.y + a2y * w1.y + h1a * u0.y + h1b * u1.y;
            acc[jb].z += a2x * w0.z + a2y * w1.z + h1a * u0.z + h1b * u1.z;
            acc[jb].w += a2x * w0.w + a2y * w1.w + h1a * u0.w + h1b * u1.w;
        }
    }

    // relu + pooling. batch is sorted -> warps almost always graph-uniform.
    bool uni = __all_sync(0xffffffffu, g == __shfl_sync(0xffffffffu, g, 0));
    float* pooledf = (float*)g_pooled;
#pragma unroll
    for (int jb = 0; jb < 16; jb++) {
        float4 v;
        v.x = fmaxf(acc[jb].x, 0.f); v.y = fmaxf(acc[jb].y, 0.f);
        v.z = fmaxf(acc[jb].z, 0.f); v.w = fmaxf(acc[jb].w, 0.f);
        if (uni) {
            for (int o = 16; o > 0; o >>= 1) {
                v.x += __shfl_xor_sync(0xffffffffu, v.x, o);
                v.y += __shfl_xor_sync(0xffffffffu, v.y, o);
                v.z += __shfl_xor_sync(0xffffffffu, v.z, o);
                v.w += __shfl_xor_sync(0xffffffffu, v.w, o);
            }
            if ((tid & 31) == 0)
                atomicAdd((float4*)(pooledf + g * HIDC + 4 * jb), v);
        } else {
            atomicAdd((float4*)(pooledf + g * HIDC + 4 * jb), v);
        }
    }
}

// ---------------- pass E: classifier ----------------
__global__ void k_cls(const float* __restrict__ Wc, const float* __restrict__ bc,
                      float* __restrict__ out) {
    __shared__ float sp[HIDC];
    int g = blockIdx.x, t = threadIdx.x;   // 32 threads
    float invg = 1.0f / fmaxf(g_gcnt[g], 1.0f);
    const float* pooledf = (const float*)g_pooled;
    sp[t] = pooledf[g * HIDC + t] * invg;
    sp[t + 32] = pooledf[g * HIDC + 32 + t] * invg;
    __syncwarp();
    if (t < NCLS) {
        float a = __ldg(&bc[t]);
#pragma unroll
        for (int j = 0; j < HIDC; j++) a += sp[j] * __ldg(&Wc[j * NCLS + t]);
        out[g * NCLS + t] = a;
    }
}

// ---------------- launch ----------------
extern "C" void kernel_launch(void* const* d_in, const int* in_sizes, int n_in,
                              void* d_out, int out_size) {
    const float* x   = (const float*)d_in[0];
    const void*  ei  = d_in[1];
    const void*  bt  = d_in[2];
    const float* W1l = (const float*)d_in[3];
    const float* b1  = (const float*)d_in[4];
    const float* W1r = (const float*)d_in[5];
    const float* W2l = (const float*)d_in[6];
    const float* b2  = (const float*)d_in[7];
    const float* W2r = (const float*)d_in[8];
    const float* Wc  = (const float*)d_in[9];
    const float* bc  = (const float*)d_in[10];
    float* out = (float*)d_out;

    k_zero<<<2048, 256>>>();
    k_detect<<<1, 256>>>((const int*)ei, (const int*)bt);
    k_edge_scalar<<<N_EDGESC / 256, 256>>>(ei, x);
    k_h1<<<N_NODESC * 16 / 256, 256>>>(x, bt, W1l, b1, W1r);
    k_edge_feat<<<N_EDGESC / 256, 256>>>(ei);
    k_h2pool<<<N_NODESC / 160, 160>>>(x, bt, W1l, b1, W1r, W2l, b2, W2r);
    k_cls<<<N_GRAPHSC, 32>>>(Wc, bc, out);
}

// round 2
// speedup vs baseline: 1.4826x; 1.4826x over previous
#include <cuda_runtime.h>

#define N_NODESC 100000
#define N_EDGESC 3200000
#define N_GRAPHSC 1024
#define HIDC 64
#define NCLS 21

// ---------------- scratch (device globals; no allocation) ----------------
__device__ int    g_rp[N_NODESC + 1];             // CSR row_ptr (by dst); counts during hist
__device__ int    g_cur[N_NODESC];                // scatter cursors
__device__ int    g_adj[N_EDGESC];                // CSR adjacency: src ids grouped by dst
__device__ float2 g_s1[N_NODESC];                 // per node {a1 = mean x[src], x}
__device__ float2 g_a2[32 * N_NODESC];            // layer-2 mean-agg, pair-major [pair][node]
__device__ float4 g_pooled[N_GRAPHSC * 16];       // pooled [G][64]
__device__ float  g_gcnt[N_GRAPHSC];
__device__ int    g_e32, g_b32;                   // 1 => indices are int32

// ---------------- zero scratch ----------------
__global__ void k_zero() {
    int i = blockIdx.x * blockDim.x + threadIdx.x;
    int stride = gridDim.x * blockDim.x;
    for (int j = i; j < N_NODESC; j += stride) g_rp[j] = 0;
    for (int j = i; j < N_GRAPHSC * 16; j += stride) g_pooled[j] = make_float4(0.f, 0.f, 0.f, 0.f);
    for (int j = i; j < N_GRAPHSC; j += stride) g_gcnt[j] = 0.f;
    if (i == 0) { g_e32 = 0; g_b32 = 0; g_rp[N_NODESC] = 0; }
}

// ---------------- dtype detection (int64 vs int32 indices) ----------------
__global__ void k_detect(const int* ei, const int* bi) {
    int t = threadIdx.x;
    int accE = 0, accB = 0;
    for (int j = t; j < 8192; j += 256) accE |= ei[2 * j + 1];
    for (int j = t; j < 2048; j += 256) accB |= bi[2 * j + 1];
    for (int o = 16; o > 0; o >>= 1) {
        accE |= __shfl_xor_sync(0xffffffffu, accE, o);
        accB |= __shfl_xor_sync(0xffffffffu, accB, o);
    }
    if ((t & 31) == 0) {
        if (accE) atomicOr(&g_e32, 1);
        if (accB) atomicOr(&g_b32, 1);
    }
}

__device__ __forceinline__ int load_idx(const void* p, long i, bool is32) {
    if (is32) return ((const int*)p)[i];
    return (int)((const long long*)p)[i];
}

// ---------------- CSR build: histogram of dst ----------------
__global__ void k_hist(const void* eptr) {
    bool e32 = (g_e32 != 0);
    long e = (long)blockIdx.x * blockDim.x + threadIdx.x;
    if (e >= N_EDGESC) return;
    int d = load_idx(eptr, N_EDGESC + e, e32);
    atomicAdd(&g_rp[d], 1);
}

// ---------------- CSR build: exclusive scan (1 block, 1024 threads) ----------------
__global__ void k_scan() {
    const int T = 1024, CH = 98;                  // 1024*98 = 100352 >= 100000
    int t = threadIdx.x;
    int begin = t * CH;
    int endi = begin + CH; if (endi > N_NODESC) endi = N_NODESC;
    int s = 0;
    for (int i = begin; i < endi; i++) s += g_rp[i];
    __shared__ int sp[T];
    sp[t] = s;
    __syncthreads();
    for (int off = 1; off < T; off <<= 1) {
        int v = (t >= off) ? sp[t - off] : 0;
        __syncthreads();
        sp[t] += v;
        __syncthreads();
    }
    int run = sp[t] - s;                          // exclusive prefix of this chunk
    for (int i = begin; i < endi; i++) {
        int c = g_rp[i];
        g_rp[i] = run;
        g_cur[i] = run;
        run += c;
    }
    if (t == T - 1) g_rp[N_NODESC] = run;
}

// ---------------- CSR build: scatter src by dst ----------------
__global__ void k_scatter(const void* eptr) {
    bool e32 = (g_e32 != 0);
    long e = (long)blockIdx.x * blockDim.x + threadIdx.x;
    if (e >= N_EDGESC) return;
    int s = load_idx(eptr, e, e32);
    int d = load_idx(eptr, N_EDGESC + e, e32);
    int pos = atomicAdd(&g_cur[d], 1);
    g_adj[pos] = s;
}

// ---------------- sweep 1: a1 = mean of x over in-neighbors; also graph counts ----------------
__global__ void k_sweep1(const float* __restrict__ x, const void* bptr) {
    int wid = (blockIdx.x * blockDim.x + threadIdx.x) >> 5;
    if (wid >= N_NODESC) return;
    int lane = threadIdx.x & 31;
    int start = g_rp[wid], end = g_rp[wid + 1];
    float sum = 0.f;
    for (int i = start + lane; i < end; i += 32) sum += __ldg(&x[g_adj[i]]);
    for (int o = 16; o > 0; o >>= 1) sum += __shfl_xor_sync(0xffffffffu, sum, o);
    if (lane == 0) {
        float deg = (float)(end - start);
        float a1 = sum / fmaxf(deg, 1.0f);
        g_s1[wid] = make_float2(a1, x[wid]);
        int g = load_idx(bptr, wid, g_b32 != 0);
        atomicAdd(&g_gcnt[g], 1.0f);
    }
}

// ---------------- sweep 2: mean-aggregate h1 (recomputed from scalars) ----------------
// warp per node, lane l owns feature pair (2l, 2l+1)
__global__ void k_sweep2(const float* __restrict__ W1l, const float* __restrict__ b1,
                         const float* __restrict__ W1r) {
    int n = (blockIdx.x * blockDim.x + threadIdx.x) >> 5;
    if (n >= N_NODESC) return;
    int lane = threadIdx.x & 31;
    float2 wl = __ldg((const float2*)W1l + lane);
    float2 wr = __ldg((const float2*)W1r + lane);
    float2 bb = __ldg((const float2*)b1 + lane);
    float2 acc = make_float2(0.f, 0.f);
    int start = g_rp[n], end = g_rp[n + 1];
    for (int base = start; base < end; base += 32) {
        int m = end - base; if (m > 32) m = 32;
        float2 sv = make_float2(0.f, 0.f);
        if (lane < m) sv = g_s1[g_adj[base + lane]];
#pragma unroll 4
        for (int j = 0; j < m; j++) {
            float a1 = __shfl_sync(0xffffffffu, sv.x, j);
            float xv = __shfl_sync(0xffffffffu, sv.y, j);
            acc.x += fmaxf(fmaf(a1, wl.x, fmaf(xv, wr.x, bb.x)), 0.f);
            acc.y += fmaxf(fmaf(a1, wl.y, fmaf(xv, wr.y, bb.y)), 0.f);
        }
    }
    float inv = 1.0f / fmaxf((float)(end - start), 1.0f);
    g_a2[(long)lane * N_NODESC + n] = make_float2(acc.x * inv, acc.y * inv);
}

// ---------------- layer-2 dense + relu + graph pooling ----------------
__global__ void __launch_bounds__(160) k_h2pool(
        const void* bptr,
        const float* __restrict__ W1l, const float* __restrict__ b1, const float* __restrict__ W1r,
        const float* __restrict__ W2l, const float* __restrict__ b2, const float* __restrict__ W2r) {
    __shared__ float sWl[HIDC * HIDC];
    __shared__ float sWr[HIDC * HIDC];
    __shared__ float sW1[3][HIDC];
    int tid = threadIdx.x;
    for (int i = tid; i < HIDC * HIDC; i += 160) { sWl[i] = W2l[i]; sWr[i] = W2r[i]; }
    if (tid < HIDC) { sW1[0][tid] = W1l[tid]; sW1[1][tid] = W1r[tid]; sW1[2][tid] = b1[tid]; }
    __syncthreads();

    int n = blockIdx.x * 160 + tid;                  // exact: 625*160 = 100000
    float2 s1 = g_s1[n];
    float a1 = s1.x, xv = s1.y;
    int g = load_idx(bptr, n, g_b32 != 0);

    float4 acc[16];
#pragma unroll
    for (int jb = 0; jb < 16; jb++) acc[jb] = __ldg((const float4*)(b2 + 4 * jb));

#pragma unroll 1
    for (int p = 0; p < 32; p++) {
        float2 a2v = g_a2[(long)p * N_NODESC + n];   // already the mean
        float a2x = a2v.x, a2y = a2v.y;
        int k0 = 2 * p, k1 = 2 * p + 1;
        float h1a = fmaxf(a1 * sW1[0][k0] + xv * sW1[1][k0] + sW1[2][k0], 0.f);
        float h1b = fmaxf(a1 * sW1[0][k1] + xv * sW1[1][k1] + sW1[2][k1], 0.f);
        const float4* wl0 = (const float4*)(sWl + k0 * HIDC);
        const float4* wl1 = (const float4*)(sWl + k1 * HIDC);
        const float4* wr0 = (const float4*)(sWr + k0 * HIDC);
        const float4* wr1 = (const float4*)(sWr + k1 * HIDC);
#pragma unroll
        for (int jb = 0; jb < 16; jb++) {
            float4 w0 = wl0[jb], w1 = wl1[jb], u0 = wr0[jb], u1 = wr1[jb];
            acc[jb].x += a2x * w0.x + a2y * w1.x + h1a * u0.x + h1b * u1.x;
            acc[jb].y += a2x * w0.y + a2y * w1.y + h1a * u0.y + h1b * u1.y;
            acc[jb].z += a2x * w0.z + a2y * w1.z + h1a * u0.z + h1b * u1.z;
            acc[jb].w += a2x * w0.w + a2y * w1.w + h1a * u0.w + h1b * u1.w;
        }
    }

    // relu + pooling. batch sorted -> warps almost always graph-uniform.
    bool uni = __all_sync(0xffffffffu, g == __shfl_sync(0xffffffffu, g, 0));
    float* pooledf = (float*)g_pooled;
#pragma unroll
    for (int jb = 0; jb < 16; jb++) {
        float4 v;
        v.x = fmaxf(acc[jb].x, 0.f); v.y = fmaxf(acc[jb].y, 0.f);
        v.z = fmaxf(acc[jb].z, 0.f); v.w = fmaxf(acc[jb].w, 0.f);
        if (uni) {
            for (int o = 16; o > 0; o >>= 1) {
                v.x += __shfl_xor_sync(0xffffffffu, v.x, o);
                v.y += __shfl_xor_sync(0xffffffffu, v.y, o);
                v.z += __shfl_xor_sync(0xffffffffu, v.z, o);
                v.w += __shfl_xor_sync(0xffffffffu, v.w, o);
            }
            if ((tid & 31) == 0)
                atomicAdd((float4*)(pooledf + g * HIDC + 4 * jb), v);
        } else {
            atomicAdd((float4*)(pooledf + g * HIDC + 4 * jb), v);
        }
    }
}

// ---------------- classifier ----------------
__global__ void k_cls(const float* __restrict__ Wc, const float* __restrict__ bc,
                      float* __restrict__ out) {
    __shared__ float sp[HIDC];
    int g = blockIdx.x, t = threadIdx.x;   // 32 threads
    float invg = 1.0f / fmaxf(g_gcnt[g], 1.0f);
    const float* pooledf = (const float*)g_pooled;
    sp[t] = pooledf[g * HIDC + t] * invg;
    sp[t + 32] = pooledf[g * HIDC + 32 + t] * invg;
    __syncwarp();
    if (t < NCLS) {
        float a = __ldg(&bc[t]);
#pragma unroll
        for (int j = 0; j < HIDC; j++) a += sp[j] * __ldg(&Wc[j * NCLS + t]);
        out[g * NCLS + t] = a;
    }
}

// ---------------- launch ----------------
extern "C" void kernel_launch(void* const* d_in, const int* in_sizes, int n_in,
                              void* d_out, int out_size) {
    const float* x   = (const float*)d_in[0];
    const void*  ei  = d_in[1];
    const void*  bt  = d_in[2];
    const float* W1l = (const float*)d_in[3];
    const float* b1  = (const float*)d_in[4];
    const float* W1r = (const float*)d_in[5];
    const float* W2l = (const float*)d_in[6];
    const float* b2  = (const float*)d_in[7];
    const float* W2r = (const float*)d_in[8];
    const float* Wc  = (const float*)d_in[9];
    const float* bc  = (const float*)d_in[10];
    float* out = (float*)d_out;

    k_zero<<<512, 256>>>();
    k_detect<<<1, 256>>>((const int*)ei, (const int*)bt);
    k_hist<<<N_EDGESC / 256, 256>>>(ei);
    k_scan<<<1, 1024>>>();
    k_scatter<<<N_EDGESC / 256, 256>>>(ei);
    k_sweep1<<<N_NODESC / 8, 256>>>(x, bt);
    k_sweep2<<<N_NODESC / 8, 256>>>(W1l, b1, W1r);
    k_h2pool<<<N_NODESC / 160, 160>>>(bt, W1l, b1, W1r, W2l, b2, W2r);
    k_cls<<<N_GRAPHSC, 32>>>(Wc, bc, out);
}

// round 3
// speedup vs baseline: 2.4013x; 1.6196x over previous
#include <cuda_runtime.h>

#define N_NODESC 100000
#define N_EDGESC 3200000
#define N_GRAPHSC 1024
#define HIDC 64
#define NCLS 21
#define SCAN_BLKS 98                              // 98 * 1024 = 100352 >= N_NODESC

// ---------------- scratch (device globals; no allocation) ----------------
__device__ int    g_rp[N_NODESC + 1];             // CSR row_ptr (by dst); counts during hist
__device__ int    g_cur[N_NODESC];                // scatter cursors
__device__ int    g_adj[N_EDGESC];                // CSR adjacency: src ids grouped by dst
__device__ int    g_bsum[SCAN_BLKS];              // scan block sums
__device__ int    g_boff[SCAN_BLKS];              // scan block offsets (exclusive)
__device__ float2 g_s1[N_NODESC];                 // per node {a1 = mean x[src], x}
__device__ float2 g_a2[32 * N_NODESC];            // layer-2 mean-agg, pair-major [pair][node]
__device__ float4 g_pooled[N_GRAPHSC * 16];       // pooled [G][64]
__device__ float  g_gcnt[N_GRAPHSC];
__device__ int    g_e32, g_b32;                   // 1 => indices are int32

// ---------------- zero scratch ----------------
__global__ void k_zero() {
    int i = blockIdx.x * blockDim.x + threadIdx.x;
    int stride = gridDim.x * blockDim.x;
    for (int j = i; j < N_NODESC; j += stride) g_rp[j] = 0;
    for (int j = i; j < N_GRAPHSC * 16; j += stride) g_pooled[j] = make_float4(0.f, 0.f, 0.f, 0.f);
    for (int j = i; j < N_GRAPHSC; j += stride) g_gcnt[j] = 0.f;
    if (i == 0) { g_e32 = 0; g_b32 = 0; g_rp[N_NODESC] = 0; }
}

// ---------------- dtype detection (int64 vs int32 indices) ----------------
__global__ void k_detect(const int* ei, const int* bi) {
    int t = threadIdx.x;
    int accE = 0, accB = 0;
    for (int j = t; j < 8192; j += 256) accE |= ei[2 * j + 1];
    for (int j = t; j < 2048; j += 256) accB |= bi[2 * j + 1];
    for (int o = 16; o > 0; o >>= 1) {
        accE |= __shfl_xor_sync(0xffffffffu, accE, o);
        accB |= __shfl_xor_sync(0xffffffffu, accB, o);
    }
    if ((t & 31) == 0) {
        if (accE) atomicOr(&g_e32, 1);
        if (accB) atomicOr(&g_b32, 1);
    }
}

__device__ __forceinline__ int load_idx(const void* p, long i, bool is32) {
    if (is32) return ((const int*)p)[i];
    return (int)((const long long*)p)[i];
}

// ---------------- CSR build: histogram of dst ----------------
__global__ void k_hist(const void* eptr) {
    bool e32 = (g_e32 != 0);
    long e = (long)blockIdx.x * blockDim.x + threadIdx.x;
    if (e >= N_EDGESC) return;
    int d = load_idx(eptr, N_EDGESC + e, e32);
    atomicAdd(&g_rp[d], 1);
}

// ---------------- parallel exclusive scan, 3 phases ----------------
__global__ void k_scan1() {                       // SCAN_BLKS blocks x 256
    int b = blockIdx.x, t = threadIdx.x;
    int base = b * 1024;
    int s = 0;
    for (int j = t; j < 1024; j += 256) {
        int i = base + j;
        s += (i < N_NODESC) ? g_rp[i] : 0;
    }
    __shared__ int red[256];
    red[t] = s; __syncthreads();
    for (int o = 128; o > 0; o >>= 1) { if (t < o) red[t] += red[t + o]; __syncthreads(); }
    if (t == 0) g_bsum[b] = red[0];
}

__global__ void k_scan2() {                       // 1 block x 128
    int t = threadIdx.x;
    __shared__ int sp[128];
    int v = (t < SCAN_BLKS) ? g_bsum[t] : 0;
    sp[t] = v; __syncthreads();
    for (int o = 1; o < 128; o <<= 1) {
        int u = (t >= o) ? sp[t - o] : 0;
        __syncthreads();
        sp[t] += u;
        __syncthreads();
    }
    if (t < SCAN_BLKS) g_boff[t] = sp[t] - v;     // exclusive block offset
    if (t == 127) g_rp[N_NODESC] = sp[127];       // total = N_EDGES
}

__global__ void k_scan3() {                       // SCAN_BLKS blocks x 256, 4 elems/thread
    int b = blockIdx.x, t = threadIdx.x;
    int base = b * 1024 + t * 4;
    int c[4];
    int s = 0;
#pragma unroll
    for (int j = 0; j < 4; j++) {
        int i = base + j;
        c[j] = (i < N_NODESC) ? g_rp[i] : 0;
        s += c[j];
    }
    __shared__ int sp[256];
    sp[t] = s; __syncthreads();
    for (int o = 1; o < 256; o <<= 1) {
        int u = (t >= o) ? sp[t - o] : 0;
        __syncthreads();
        sp[t] += u;
        __syncthreads();
    }
    int run = g_boff[b] + sp[t] - s;              // exclusive prefix for this thread
#pragma unroll
    for (int j = 0; j < 4; j++) {
        int i = base + j;
        if (i < N_NODESC) { g_rp[i] = run; g_cur[i] = run; run += c[j]; }
    }
}

// ---------------- CSR build: scatter src by dst ----------------
__global__ void k_scatter(const void* eptr) {
    bool e32 = (g_e32 != 0);
    long e = (long)blockIdx.x * blockDim.x + threadIdx.x;
    if (e >= N_EDGESC) return;
    int s = load_idx(eptr, e, e32);
    int d = load_idx(eptr, N_EDGESC + e, e32);
    int pos = atomicAdd(&g_cur[d], 1);
    g_adj[pos] = s;
}

// ---------------- sweep 1: a1 = mean of x over in-neighbors; also graph counts ----------------
__global__ void k_sweep1(const float* __restrict__ x, const void* bptr) {
    int wid = (blockIdx.x * blockDim.x + threadIdx.x) >> 5;
    if (wid >= N_NODESC) return;
    int lane = threadIdx.x & 31;
    int start = g_rp[wid], end = g_rp[wid + 1];
    float sum = 0.f;
    for (int i = start + lane; i < end; i += 32) sum += __ldg(&x[g_adj[i]]);
    for (int o = 16; o > 0; o >>= 1) sum += __shfl_xor_sync(0xffffffffu, sum, o);
    if (lane == 0) {
        float deg = (float)(end - start);
        float a1 = sum / fmaxf(deg, 1.0f);
        g_s1[wid] = make_float2(a1, x[wid]);
        int g = load_idx(bptr, wid, g_b32 != 0);
        atomicAdd(&g_gcnt[g], 1.0f);
    }
}

// ---------------- sweep 2: mean-aggregate h1 (recomputed from scalars) ----------------
// warp per node, lane l owns feature pair (2l, 2l+1)
__global__ void k_sweep2(const float* __restrict__ W1l, const float* __restrict__ b1,
                         const float* __restrict__ W1r) {
    int n = (blockIdx.x * blockDim.x + threadIdx.x) >> 5;
    if (n >= N_NODESC) return;
    int lane = threadIdx.x & 31;
    float2 wl = __ldg((const float2*)W1l + lane);
    float2 wr = __ldg((const float2*)W1r + lane);
    float2 bb = __ldg((const float2*)b1 + lane);
    float2 acc = make_float2(0.f, 0.f);
    int start = g_rp[n], end = g_rp[n + 1];
    for (int base = start; base < end; base += 32) {
        int m = end - base; if (m > 32) m = 32;
        float2 sv = make_float2(0.f, 0.f);
        if (lane < m) sv = g_s1[g_adj[base + lane]];
#pragma unroll 4
        for (int j = 0; j < m; j++) {
            float a1 = __shfl_sync(0xffffffffu, sv.x, j);
            float xv = __shfl_sync(0xffffffffu, sv.y, j);
            acc.x += fmaxf(fmaf(a1, wl.x, fmaf(xv, wr.x, bb.x)), 0.f);
            acc.y += fmaxf(fmaf(a1, wl.y, fmaf(xv, wr.y, bb.y)), 0.f);
        }
    }
    float inv = 1.0f / fmaxf((float)(end - start), 1.0f);
    g_a2[(long)lane * N_NODESC + n] = make_float2(acc.x * inv, acc.y * inv);
}

// ---------------- layer-2 dense + relu + graph pooling ----------------
__global__ void __launch_bounds__(160) k_h2pool(
        const void* bptr,
        const float* __restrict__ W1l, const float* __restrict__ b1, const float* __restrict__ W1r,
        const float* __restrict__ W2l, const float* __restrict__ b2, const float* __restrict__ W2r) {
    __shared__ float sWl[HIDC * HIDC];
    __shared__ float sWr[HIDC * HIDC];
    __shared__ float sW1[3][HIDC];
    int tid = threadIdx.x;
    for (int i = tid; i < HIDC * HIDC; i += 160) { sWl[i] = W2l[i]; sWr[i] = W2r[i]; }
    if (tid < HIDC) { sW1[0][tid] = W1l[tid]; sW1[1][tid] = W1r[tid]; sW1[2][tid] = b1[tid]; }
    __syncthreads();

    int n = blockIdx.x * 160 + tid;                  // exact: 625*160 = 100000
    float2 s1 = g_s1[n];
    float a1 = s1.x, xv = s1.y;
    int g = load_idx(bptr, n, g_b32 != 0);

    float4 acc[16];
#pragma unroll
    for (int jb = 0; jb < 16; jb++) acc[jb] = __ldg((const float4*)(b2 + 4 * jb));

#pragma unroll 1
    for (int p = 0; p < 32; p++) {
        float2 a2v = g_a2[(long)p * N_NODESC + n];   // already the mean
        float a2x = a2v.x, a2y = a2v.y;
        int k0 = 2 * p, k1 = 2 * p + 1;
        float h1a = fmaxf(a1 * sW1[0][k0] + xv * sW1[1][k0] + sW1[2][k0], 0.f);
        float h1b = fmaxf(a1 * sW1[0][k1] + xv * sW1[1][k1] + sW1[2][k1], 0.f);
        const float4* wl0 = (const float4*)(sWl + k0 * HIDC);
        const float4* wl1 = (const float4*)(sWl + k1 * HIDC);
        const float4* wr0 = (const float4*)(sWr + k0 * HIDC);
        const float4* wr1 = (const float4*)(sWr + k1 * HIDC);
#pragma unroll
        for (int jb = 0; jb < 16; jb++) {
            float4 w0 = wl0[jb], w1 = wl1[jb], u0 = wr0[jb], u1 = wr1[jb];
            acc[jb].x += a2x * w0.x + a2y * w1.x + h1a * u0.x + h1b * u1.x;
            acc[jb].y += a2x * w0.y + a2y * w1.y + h1a * u0.y + h1b * u1.y;
            acc[jb].z += a2x * w0.z + a2y * w1.z + h1a * u0.z + h1b * u1.z;
            acc[jb].w += a2x * w0.w + a2y * w1.w + h1a * u0.w + h1b * u1.w;
        }
    }

    // relu + pooling. batch sorted -> warps almost always graph-uniform.
    bool uni = __all_sync(0xffffffffu, g == __shfl_sync(0xffffffffu, g, 0));
    float* pooledf = (float*)g_pooled;
#pragma unroll
    for (int jb = 0; jb < 16; jb++) {
        float4 v;
        v.x = fmaxf(acc[jb].x, 0.f); v.y = fmaxf(acc[jb].y, 0.f);
        v.z = fmaxf(acc[jb].z, 0.f); v.w = fmaxf(acc[jb].w, 0.f);
        if (uni) {
            for (int o = 16; o > 0; o >>= 1) {
                v.x += __shfl_xor_sync(0xffffffffu, v.x, o);
                v.y += __shfl_xor_sync(0xffffffffu, v.y, o);
                v.z += __shfl_xor_sync(0xffffffffu, v.z, o);
                v.w += __shfl_xor_sync(0xffffffffu, v.w, o);
            }
            if ((tid & 31) == 0)
                atomicAdd((float4*)(pooledf + g * HIDC + 4 * jb), v);
        } else {
            atomicAdd((float4*)(pooledf + g * HIDC + 4 * jb), v);
        }
    }
}

// ---------------- classifier ----------------
__global__ void k_cls(const float* __restrict__ Wc, const float* __restrict__ bc,
                      float* __restrict__ out) {
    __shared__ float sp[HIDC];
    int g = blockIdx.x, t = threadIdx.x;   // 32 threads
    float invg = 1.0f / fmaxf(g_gcnt[g], 1.0f);
    const float* pooledf = (const float*)g_pooled;
    sp[t] = pooledf[g * HIDC + t] * invg;
    sp[t + 32] = pooledf[g * HIDC + 32 + t] * invg;
    __syncwarp();
    if (t < NCLS) {
        float a = __ldg(&bc[t]);
#pragma unroll
        for (int j = 0; j < HIDC; j++) a += sp[j] * __ldg(&Wc[j * NCLS + t]);
        out[g * NCLS + t] = a;
    }
}

// ---------------- launch ----------------
extern "C" void kernel_launch(void* const* d_in, const int* in_sizes, int n_in,
                              void* d_out, int out_size) {
    const float* x   = (const float*)d_in[0];
    const void*  ei  = d_in[1];
    const void*  bt  = d_in[2];
    const float* W1l = (const float*)d_in[3];
    const float* b1  = (const float*)d_in[4];
    const float* W1r = (const float*)d_in[5];
    const float* W2l = (const float*)d_in[6];
    const float* b2  = (const float*)d_in[7];
    const float* W2r = (const float*)d_in[8];
    const float* Wc  = (const float*)d_in[9];
    const float* bc  = (const float*)d_in[10];
    float* out = (float*)d_out;

    k_zero<<<512, 256>>>();
    k_detect<<<1, 256>>>((const int*)ei, (const int*)bt);
    k_hist<<<N_EDGESC / 256, 256>>>(ei);
    k_scan1<<<SCAN_BLKS, 256>>>();
    k_scan2<<<1, 128>>>();
    k_scan3<<<SCAN_BLKS, 256>>>();
    k_scatter<<<N_EDGESC / 256, 256>>>(ei);
    k_sweep1<<<N_NODESC / 8, 256>>>(x, bt);
    k_sweep2<<<N_NODESC / 8, 256>>>(W1l, b1, W1r);
    k_h2pool<<<N_NODESC / 160, 160>>>(bt, W1l, b1, W1r, W2l, b2, W2r);
    k_cls<<<N_GRAPHSC, 32>>>(Wc, bc, out);
}

// round 5
// speedup vs baseline: 2.5653x; 1.0683x over previous
#include <cuda_runtime.h>

#define N_NODESC 100000
#define N_EDGESC 3200000
#define N_GRAPHSC 1024
#define HIDC 64
#define NCLS 21
#define SCAN_BLKS 98                              // 98 * 1024 = 100352 >= N_NODESC

// ---------------- scratch (device globals; no allocation) ----------------
__device__ int    g_rp[N_NODESC + 1];             // CSR row_ptr (by dst); counts during hist
__device__ int    g_cur[N_NODESC];                // scatter cursors
__device__ int    g_adj[N_EDGESC];                // CSR adjacency: src ids grouped by dst
__device__ int    g_bsum[SCAN_BLKS];              // scan block sums
__device__ int    g_boff[SCAN_BLKS];              // scan block offsets (exclusive)
__device__ float  g_scx[N_NODESC];                // sum of x[src] per dst (fused into scatter)
__device__ float2 g_s1[N_NODESC];                 // per node {a1 = mean x[src], x}
__device__ float2 g_a2[32 * N_NODESC];            // layer-2 mean-agg, pair-major [pair][node]
__device__ float4 g_pooled[N_GRAPHSC * 16];       // pooled [G][64]
__device__ float  g_gcnt[N_GRAPHSC];
__device__ int    g_e32, g_b32;                   // 1 => indices are int32

// packed f32x2 helpers (sm_103a: FFMA2 only reachable via PTX)
#define FMA2(acc, m, w) asm("fma.rn.f32x2 %0, %1, %2, %0;" : "+d"(acc) : "d"(m), "d"(w))
__device__ __forceinline__ double pack2(float v) {
    double d;
    asm("mov.b64 %0, {%1, %1};" : "=d"(d) : "r"(__float_as_uint(v)));
    return d;
}

// ---------------- zero scratch + detect dtypes ----------------
__global__ void k_zero(const int* ei, const int* bi) {
    int i = blockIdx.x * blockDim.x + threadIdx.x;
    int stride = gridDim.x * blockDim.x;
    for (int j = i; j < N_NODESC; j += stride) { g_rp[j] = 0; g_scx[j] = 0.f; }
    for (int j = i; j < N_GRAPHSC * 16; j += stride) g_pooled[j] = make_float4(0.f, 0.f, 0.f, 0.f);
    for (int j = i; j < N_GRAPHSC; j += stride) g_gcnt[j] = 0.f;
    if (i == 0) { g_e32 = 0; g_b32 = 0; g_rp[N_NODESC] = 0; }
    // dtype detection (block 0 only): int64 small values => odd 32-bit words all 0
    if (blockIdx.x == 0) {
        int t = threadIdx.x;
        int accE = 0, accB = 0;
        for (int j = t; j < 8192; j += 256) accE |= ei[2 * j + 1];
        for (int j = t; j < 2048; j += 256) accB |= bi[2 * j + 1];
        for (int o = 16; o > 0; o >>= 1) {
            accE |= __shfl_xor_sync(0xffffffffu, accE, o);
            accB |= __shfl_xor_sync(0xffffffffu, accB, o);
        }
        if ((t & 31) == 0) {
            if (accE) atomicOr(&g_e32, 1);
            if (accB) atomicOr(&g_b32, 1);
        }
    }
}

__device__ __forceinline__ int load_idx(const void* p, long i, bool is32) {
    if (is32) return ((const int*)p)[i];
    return (int)((const long long*)p)[i];
}

// ---------------- CSR build: histogram of dst ----------------
__global__ void k_hist(const void* eptr) {
    bool e32 = (g_e32 != 0);
    long e = (long)blockIdx.x * blockDim.x + threadIdx.x;
    if (e >= N_EDGESC) return;
    int d = load_idx(eptr, N_EDGESC + e, e32);
    atomicAdd(&g_rp[d], 1);
}

// ---------------- parallel exclusive scan, 3 phases ----------------
__global__ void k_scan1() {                       // SCAN_BLKS blocks x 256
    int b = blockIdx.x, t = threadIdx.x;
    int base = b * 1024;
    int s = 0;
    for (int j = t; j < 1024; j += 256) {
        int i = base + j;
        s += (i < N_NODESC) ? g_rp[i] : 0;
    }
    __shared__ int red[256];
    red[t] = s; __syncthreads();
    for (int o = 128; o > 0; o >>= 1) { if (t < o) red[t] += red[t + o]; __syncthreads(); }
    if (t == 0) g_bsum[b] = red[0];
}

__global__ void k_scan2() {                       // 1 block x 128
    int t = threadIdx.x;
    __shared__ int sp[128];
    int v = (t < SCAN_BLKS) ? g_bsum[t] : 0;
    sp[t] = v; __syncthreads();
    for (int o = 1; o < 128; o <<= 1) {
        int u = (t >= o) ? sp[t - o] : 0;
        __syncthreads();
        sp[t] += u;
        __syncthreads();
    }
    if (t < SCAN_BLKS) g_boff[t] = sp[t] - v;     // exclusive block offset
    if (t == 127) g_rp[N_NODESC] = sp[127];       // total = N_EDGES
}

__global__ void k_scan3() {                       // SCAN_BLKS blocks x 256, 4 elems/thread
    int b = blockIdx.x, t = threadIdx.x;
    int base = b * 1024 + t * 4;
    int c[4];
    int s = 0;
#pragma unroll
    for (int j = 0; j < 4; j++) {
        int i = base + j;
        c[j] = (i < N_NODESC) ? g_rp[i] : 0;
        s += c[j];
    }
    __shared__ int sp[256];
    sp[t] = s; __syncthreads();
    for (int o = 1; o < 256; o <<= 1) {
        int u = (t >= o) ? sp[t - o] : 0;
        __syncthreads();
        sp[t] += u;
        __syncthreads();
    }
    int run = g_boff[b] + sp[t] - s;              // exclusive prefix for this thread
#pragma unroll
    for (int j = 0; j < 4; j++) {
        int i = base + j;
        if (i < N_NODESC) { g_rp[i] = run; g_cur[i] = run; run += c[j]; }
    }
}

// ---------------- CSR build: scatter src by dst + fused scalar aggregation ----------------
__global__ void k_scatter(const void* eptr, const float* __restrict__ x) {
    bool e32 = (g_e32 != 0);
    long e = (long)blockIdx.x * blockDim.x + threadIdx.x;
    if (e >= N_EDGESC) return;
    int s = load_idx(eptr, e, e32);
    int d = load_idx(eptr, N_EDGESC + e, e32);
    int pos = atomicAdd(&g_cur[d], 1);
    g_adj[pos] = s;
    atomicAdd(&g_scx[d], __ldg(&x[s]));           // REDG.F32 (degree comes from row_ptr)
}

// ---------------- finalize layer-1 scalars + graph counts ----------------
__global__ void k_s1(const float* __restrict__ x, const void* bptr) {
    int n = blockIdx.x * blockDim.x + threadIdx.x;
    if (n >= N_NODESC) return;
    float deg = (float)(g_rp[n + 1] - g_rp[n]);
    float a1 = g_scx[n] / fmaxf(deg, 1.0f);
    g_s1[n] = make_float2(a1, x[n]);
    int g = load_idx(bptr, n, g_b32 != 0);
    atomicAdd(&g_gcnt[g], 1.0f);
}

// ---------------- sweep 2: mean-aggregate h1 (recomputed from scalars) ----------------
// warp per node, lane l owns feature pair (2l, 2l+1)
__global__ void k_sweep2(const float* __restrict__ W1l, const float* __restrict__ b1,
                         const float* __restrict__ W1r) {
    int n = (blockIdx.x * blockDim.x + threadIdx.x) >> 5;
    if (n >= N_NODESC) return;
    int lane = threadIdx.x & 31;
    float2 wl = __ldg((const float2*)W1l + lane);
    float2 wr = __ldg((const float2*)W1r + lane);
    float2 bb = __ldg((const float2*)b1 + lane);
    float2 acc = make_float2(0.f, 0.f);
    int start = g_rp[n], end = g_rp[n + 1];
    for (int base = start; base < end; base += 32) {
        int m = end - base; if (m > 32) m = 32;
        float2 sv = make_float2(0.f, 0.f);
        if (lane < m) sv = g_s1[g_adj[base + lane]];
#pragma unroll 4
        for (int j = 0; j < m; j++) {
            float a1 = __shfl_sync(0xffffffffu, sv.x, j);
            float xv = __shfl_sync(0xffffffffu, sv.y, j);
            acc.x += fmaxf(fmaf(a1, wl.x, fmaf(xv, wr.x, bb.x)), 0.f);
            acc.y += fmaxf(fmaf(a1, wl.y, fmaf(xv, wr.y, bb.y)), 0.f);
        }
    }
    float inv = 1.0f / fmaxf((float)(end - start), 1.0f);
    g_a2[(long)lane * N_NODESC + n] = make_float2(acc.x * inv, acc.y * inv);
}

// ---------------- layer-2 dense (packed f32x2) + relu + graph pooling ----------------
__global__ void __launch_bounds__(160) k_h2pool(
        const void* bptr,
        const float* __restrict__ W1l, const float* __restrict__ b1, const float* __restrict__ W1r,
        const float* __restrict__ W2l, const float* __restrict__ b2, const float* __restrict__ W2r) {
    __shared__ float sWl[HIDC * HIDC];
    __shared__ float sWr[HIDC * HIDC];
    __shared__ float sW1[3][HIDC];
    int tid = threadIdx.x;
    for (int i = tid; i < HIDC * HIDC; i += 160) { sWl[i] = W2l[i]; sWr[i] = W2r[i]; }
    if (tid < HIDC) { sW1[0][tid] = W1l[tid]; sW1[1][tid] = W1r[tid]; sW1[2][tid] = b1[tid]; }
    __syncthreads();

    int n = blockIdx.x * 160 + tid;                  // exact: 625*160 = 100000
    float2 s1 = g_s1[n];
    float a1 = s1.x, xv = s1.y;
    int g = load_idx(bptr, n, g_b32 != 0);

    // 64 accumulators as 32 packed f32x2 pairs (feature 2q, 2q+1 in acc2[q])
    double acc2[32];
    const double* b2d = (const double*)b2;
#pragma unroll
    for (int q = 0; q < 32; q++) acc2[q] = __ldg(&b2d[q]);

#pragma unroll 1
    for (int p = 0; p < 32; p++) {
        float2 a2v = g_a2[(long)p * N_NODESC + n];   // already the mean
        int k0 = 2 * p, k1 = 2 * p + 1;
        float h1a = fmaxf(a1 * sW1[0][k0] + xv * sW1[1][k0] + sW1[2][k0], 0.f);
        float h1b = fmaxf(a1 * sW1[0][k1] + xv * sW1[1][k1] + sW1[2][k1], 0.f);
        double pa = pack2(a2v.x), pb = pack2(a2v.y);
        double ph = pack2(h1a),   pi = pack2(h1b);
        const double2* wl0 = (const double2*)(sWl + k0 * HIDC);  // 16 double2 per row
        const double2* wl1 = (const double2*)(sWl + k1 * HIDC);
        const double2* wr0 = (const double2*)(sWr + k0 * HIDC);
        const double2* wr1 = (const double2*)(sWr + k1 * HIDC);
#pragma unroll
        for (int jb = 0; jb < 16; jb++) {
            double2 w0 = wl0[jb], w1 = wl1[jb], u0 = wr0[jb], u1 = wr1[jb];
            FMA2(acc2[2 * jb],     pa, w0.x); FMA2(acc2[2 * jb + 1], pa, w0.y);
            FMA2(acc2[2 * jb],     pb, w1.x); FMA2(acc2[2 * jb + 1], pb, w1.y);
            FMA2(acc2[2 * jb],     ph, u0.x); FMA2(acc2[2 * jb + 1], ph, u0.y);
            FMA2(acc2[2 * jb],     pi, u1.x); FMA2(acc2[2 * jb + 1], pi, u1.y);
        }
    }

    // relu + pooling. batch sorted -> warps almost always graph-uniform.
    bool uni = __all_sync(0xffffffffu, g == __shfl_sync(0xffffffffu, g, 0));
    float* pooledf = (float*)g_pooled;
#pragma unroll
    for (int jb = 0; jb < 16; jb++) {
        double p0 = acc2[2 * jb], p1 = acc2[2 * jb + 1];
        float4 v;
        v.x = fmaxf(__int_as_float(__double2loint(p0)), 0.f);
        v.y = fmaxf(__int_as_float(__double2hiint(p0)), 0.f);
        v.z = fmaxf(__int_as_float(__double2loint(p1)), 0.f);
        v.w = fmaxf(__int_as_float(__double2hiint(p1)), 0.f);
        if (uni) {
            for (int o = 16; o > 0; o >>= 1) {
                v.x += __shfl_xor_sync(0xffffffffu, v.x, o);
                v.y += __shfl_xor_sync(0xffffffffu, v.y, o);
                v.z += __shfl_xor_sync(0xffffffffu, v.z, o);
                v.w += __shfl_xor_sync(0xffffffffu, v.w, o);
            }
            if ((tid & 31) == 0)
                atomicAdd((float4*)(pooledf + g * HIDC + 4 * jb), v);
        } else {
            atomicAdd((float4*)(pooledf + g * HIDC + 4 * jb), v);
        }
    }
}

// ---------------- classifier ----------------
__global__ void k_cls(const float* __restrict__ Wc, const float* __restrict__ bc,
                      float* __restrict__ out) {
    __shared__ float sp[HIDC];
    int g = blockIdx.x, t = threadIdx.x;   // 32 threads
    float invg = 1.0f / fmaxf(g_gcnt[g], 1.0f);
    const float* pooledf = (const float*)g_pooled;
    sp[t] = pooledf[g * HIDC + t] * invg;
    sp[t + 32] = pooledf[g * HIDC + 32 + t] * invg;
    __syncwarp();
    if (t < NCLS) {
        float a = __ldg(&bc[t]);
#pragma unroll
        for (int j = 0; j < HIDC; j++) a += sp[j] * __ldg(&Wc[j * NCLS + t]);
        out[g * NCLS + t] = a;
    }
}

// ---------------- launch ----------------
extern "C" void kernel_launch(void* const* d_in, const int* in_sizes, int n_in,
                              void* d_out, int out_size) {
    const float* x   = (const float*)d_in[0];
    const void*  ei  = d_in[1];
    const void*  bt  = d_in[2];
    const float* W1l = (const float*)d_in[3];
    const float* b1  = (const float*)d_in[4];
    const float* W1r = (const float*)d_in[5];
    const float* W2l = (const float*)d_in[6];
    const float* b2  = (const float*)d_in[7];
    const float* W2r = (const float*)d_in[8];
    const float* Wc  = (const float*)d_in[9];
    const float* bc  = (const float*)d_in[10];
    float* out = (float*)d_out;

    k_zero<<<512, 256>>>((const int*)ei, (const int*)bt);
    k_hist<<<N_EDGESC / 256, 256>>>(ei);
    k_scan1<<<SCAN_BLKS, 256>>>();
    k_scan2<<<1, 128>>>();
    k_scan3<<<SCAN_BLKS, 256>>>();
    k_scatter<<<N_EDGESC / 256, 256>>>(ei, x);
    k_s1<<<(N_NODESC + 255) / 256, 256>>>(x, bt);
    k_sweep2<<<N_NODESC / 8, 256>>>(W1l, b1, W1r);
    k_h2pool<<<N_NODESC / 160, 160>>>(bt, W1l, b1, W1r, W2l, b2, W2r);
    k_cls<<<N_GRAPHSC, 32>>>(Wc, bc, out);
}

// round 6
// speedup vs baseline: 2.6925x; 1.0496x over previous
#include <cuda_runtime.h>

#define N_NODESC 100000
#define N_EDGESC 3200000
#define N_GRAPHSC 1024
#define HIDC 64
#define NCLS 21
#define SCAN_BLKS 98                              // 98 * 1024 = 100352 >= N_NODESC
#define PACK_SHIFT 42
#define PACK_MASK ((1ULL << PACK_SHIFT) - 1ULL)
#define FIX_SCALE 4194304.0f                      // 2^22
#define FIX_BIAS (1 << 30)

// ---------------- scratch (device globals; no allocation) ----------------
__device__ int                g_rp[N_NODESC + 1]; // CSR row_ptr (by dst); counts during hist
__device__ unsigned long long g_pack[N_NODESC];   // {cursor:22 | biased fixed sum x: 42}
__device__ int                g_adj[N_EDGESC];    // CSR adjacency: src ids grouped by dst
__device__ unsigned int       g_pub[SCAN_BLKS];   // scan publication: 0=invalid else total+1
__device__ float2             g_s1[N_NODESC];     // per node {a1 = mean x[src], x}
__device__ float2             g_a2[32 * N_NODESC];// layer-2 mean-agg, pair-major [pair][node]
__device__ float4             g_pooled[N_GRAPHSC * 16];
__device__ float              g_gcnt[N_GRAPHSC];
__device__ int                g_e32, g_b32;       // 1 => indices are int32

// packed f32x2 helpers (sm_103a: FFMA2 only reachable via PTX)
#define FMA2(acc, m, w) asm("fma.rn.f32x2 %0, %1, %2, %0;" : "+d"(acc) : "d"(m), "d"(w))
__device__ __forceinline__ double pack2(float v) {
    double d;
    asm("mov.b64 %0, {%1, %1};" : "=d"(d) : "r"(__float_as_uint(v)));
    return d;
}

// ---------------- zero scratch + detect dtypes ----------------
__global__ void k_zero(const int* ei, const int* bi) {
    int i = blockIdx.x * blockDim.x + threadIdx.x;
    int stride = gridDim.x * blockDim.x;
    for (int j = i; j < N_NODESC; j += stride) g_rp[j] = 0;
    for (int j = i; j < N_GRAPHSC * 16; j += stride) g_pooled[j] = make_float4(0.f, 0.f, 0.f, 0.f);
    for (int j = i; j < N_GRAPHSC; j += stride) g_gcnt[j] = 0.f;
    if (i < SCAN_BLKS) g_pub[i] = 0u;
    if (i == 0) { g_e32 = 0; g_b32 = 0; g_rp[N_NODESC] = 0; }
    // dtype detection (block 0): int64 small values => odd 32-bit words all 0
    if (blockIdx.x == 0) {
        int t = threadIdx.x;
        int accE = 0, accB = 0;
        for (int j = t; j < 8192; j += 256) accE |= ei[2 * j + 1];
        for (int j = t; j < 2048; j += 256) accB |= bi[2 * j + 1];
        for (int o = 16; o > 0; o >>= 1) {
            accE |= __shfl_xor_sync(0xffffffffu, accE, o);
            accB |= __shfl_xor_sync(0xffffffffu, accB, o);
        }
        if ((t & 31) == 0) {
            if (accE) atomicOr(&g_e32, 1);
            if (accB) atomicOr(&g_b32, 1);
        }
    }
}

__device__ __forceinline__ int load_idx(const void* p, long i, bool is32) {
    if (is32) return ((const int*)p)[i];
    return (int)((const long long*)p)[i];
}

// ---------------- CSR build: histogram of dst (4 edges/thread, 16B loads) ----------------
__global__ void k_hist(const void* eptr) {
    long e = (long)(blockIdx.x * blockDim.x + threadIdx.x) * 4;
    if (e >= N_EDGESC) return;
    int d0, d1, d2, d3;
    if (g_e32 != 0) {
        int4 v = *(const int4*)((const int*)eptr + N_EDGESC + e);
        d0 = v.x; d1 = v.y; d2 = v.z; d3 = v.w;
    } else {
        const longlong2* p = (const longlong2*)((const long long*)eptr + N_EDGESC + e);
        longlong2 a = p[0], b = p[1];
        d0 = (int)a.x; d1 = (int)a.y; d2 = (int)b.x; d3 = (int)b.y;
    }
    atomicAdd(&g_rp[d0], 1);
    atomicAdd(&g_rp[d1], 1);
    atomicAdd(&g_rp[d2], 1);
    atomicAdd(&g_rp[d3], 1);
}

// ---------------- single-kernel exclusive scan (98 resident blocks) ----------------
__global__ void k_scan() {
    int b = blockIdx.x, t = threadIdx.x;
    int base = b * 1024 + t * 4;
    int c[4], s = 0;
#pragma unroll
    for (int j = 0; j < 4; j++) {
        int i = base + j;
        c[j] = (i < N_NODESC) ? g_rp[i] : 0;
        s += c[j];
    }
    __shared__ int sp[256];
    sp[t] = s; __syncthreads();
    for (int o = 1; o < 256; o <<= 1) {
        int u = (t >= o) ? sp[t - o] : 0;
        __syncthreads();
        sp[t] += u;
        __syncthreads();
    }
    int excl = sp[t] - s;
    int total = sp[255];
    __syncthreads();
    // publish this block's aggregate (single word -> no extra fence needed)
    if (t == 0) atomicExch(&g_pub[b], (unsigned)total + 1u);
    // poll predecessors: thread t handles predecessor t (t < b)
    int myv = 0;
    if (t < b) {
        unsigned v;
        do { v = *(volatile unsigned*)&g_pub[t]; } while (v == 0u);
        myv = (int)(v - 1u);
    }
    sp[t] = myv; __syncthreads();
    for (int o = 128; o > 0; o >>= 1) { if (t < o) sp[t] += sp[t + o]; __syncthreads(); }
    int offset = sp[0];
    int run = offset + excl;
#pragma unroll
    for (int j = 0; j < 4; j++) {
        int i = base + j;
        if (i < N_NODESC) {
            g_rp[i] = run;
            g_pack[i] = ((unsigned long long)run) << PACK_SHIFT;   // cursor init
            run += c[j];
        }
    }
    if (b == SCAN_BLKS - 1 && t == 255) g_rp[N_NODESC] = offset + total;
}

// ---------------- CSR scatter + fused scalar agg: ONE atomic per edge ----------------
__global__ void k_scatter(const void* eptr, const float* __restrict__ x) {
    long e = (long)(blockIdx.x * blockDim.x + threadIdx.x) * 2;
    if (e >= N_EDGESC) return;
    int s0, s1i, d0, d1;
    if (g_e32 != 0) {
        int2 sv = *(const int2*)((const int*)eptr + e);
        int2 dv = *(const int2*)((const int*)eptr + N_EDGESC + e);
        s0 = sv.x; s1i = sv.y; d0 = dv.x; d1 = dv.y;
    } else {
        longlong2 sv = *(const longlong2*)((const long long*)eptr + e);
        longlong2 dv = *(const longlong2*)((const long long*)eptr + N_EDGESC + e);
        s0 = (int)sv.x; s1i = (int)sv.y; d0 = (int)dv.x; d1 = (int)dv.y;
    }
    float x0 = __ldg(&x[s0]), x1 = __ldg(&x[s1i]);
    unsigned long long a0 = (1ULL << PACK_SHIFT) |
        (unsigned long long)(unsigned)(__float2int_rn(x0 * FIX_SCALE) + FIX_BIAS);
    unsigned long long a1 = (1ULL << PACK_SHIFT) |
        (unsigned long long)(unsigned)(__float2int_rn(x1 * FIX_SCALE) + FIX_BIAS);
    unsigned long long o0 = atomicAdd(&g_pack[d0], a0);
    unsigned long long o1 = atomicAdd(&g_pack[d1], a1);
    g_adj[o0 >> PACK_SHIFT] = s0;
    g_adj[o1 >> PACK_SHIFT] = s1i;
}

// ---------------- finalize layer-1 scalars + graph counts ----------------
__global__ void k_s1(const float* __restrict__ x, const void* bptr) {
    int n = blockIdx.x * blockDim.x + threadIdx.x;
    if (n >= N_NODESC) return;
    int deg = g_rp[n + 1] - g_rp[n];
    unsigned long long p = g_pack[n];
    long long sfx = (long long)(p & PACK_MASK) - (long long)deg * (long long)FIX_BIAS;
    float a1 = ((float)sfx * (1.0f / FIX_SCALE)) / fmaxf((float)deg, 1.0f);
    g_s1[n] = make_float2(a1, x[n]);
    int g = load_idx(bptr, n, g_b32 != 0);
    atomicAdd(&g_gcnt[g], 1.0f);
}

// ---------------- sweep 2: mean-aggregate h1 (recomputed from scalars) ----------------
// warp per node, lane l owns feature pair (2l, 2l+1)
__global__ void k_sweep2(const float* __restrict__ W1l, const float* __restrict__ b1,
                         const float* __restrict__ W1r) {
    int n = (blockIdx.x * blockDim.x + threadIdx.x) >> 5;
    if (n >= N_NODESC) return;
    int lane = threadIdx.x & 31;
    float2 wl = __ldg((const float2*)W1l + lane);
    float2 wr = __ldg((const float2*)W1r + lane);
    float2 bb = __ldg((const float2*)b1 + lane);
    float2 acc = make_float2(0.f, 0.f);
    int start = g_rp[n], end = g_rp[n + 1];
    for (int base = start; base < end; base += 32) {
        int m = end - base; if (m > 32) m = 32;
        float2 sv = make_float2(0.f, 0.f);
        if (lane < m) sv = g_s1[g_adj[base + lane]];
#pragma unroll 4
        for (int j = 0; j < m; j++) {
            float a1 = __shfl_sync(0xffffffffu, sv.x, j);
            float xv = __shfl_sync(0xffffffffu, sv.y, j);
            acc.x += fmaxf(fmaf(a1, wl.x, fmaf(xv, wr.x, bb.x)), 0.f);
            acc.y += fmaxf(fmaf(a1, wl.y, fmaf(xv, wr.y, bb.y)), 0.f);
        }
    }
    float inv = 1.0f / fmaxf((float)(end - start), 1.0f);
    g_a2[(long)lane * N_NODESC + n] = make_float2(acc.x * inv, acc.y * inv);
}

// ---------------- layer-2 dense (packed f32x2) + relu + graph pooling ----------------
__global__ void __launch_bounds__(160) k_h2pool(
        const void* bptr,
        const float* __restrict__ W1l, const float* __restrict__ b1, const float* __restrict__ W1r,
        const float* __restrict__ W2l, const float* __restrict__ b2, const float* __restrict__ W2r) {
    __shared__ float sWl[HIDC * HIDC];
    __shared__ float sWr[HIDC * HIDC];
    __shared__ float sW1[3][HIDC];
    int tid = threadIdx.x;
    for (int i = tid; i < HIDC * HIDC; i += 160) { sWl[i] = W2l[i]; sWr[i] = W2r[i]; }
    if (tid < HIDC) { sW1[0][tid] = W1l[tid]; sW1[1][tid] = W1r[tid]; sW1[2][tid] = b1[tid]; }
    __syncthreads();

    int n = blockIdx.x * 160 + tid;                  // exact: 625*160 = 100000
    float2 s1 = g_s1[n];
    float a1 = s1.x, xv = s1.y;
    int g = load_idx(bptr, n, g_b32 != 0);

    double acc2[32];
    const double* b2d = (const double*)b2;
#pragma unroll
    for (int q = 0; q < 32; q++) acc2[q] = __ldg(&b2d[q]);

#pragma unroll 1
    for (int p = 0; p < 32; p++) {
        float2 a2v = g_a2[(long)p * N_NODESC + n];   // already the mean
        int k0 = 2 * p, k1 = 2 * p + 1;
        float h1a = fmaxf(a1 * sW1[0][k0] + xv * sW1[1][k0] + sW1[2][k0], 0.f);
        float h1b = fmaxf(a1 * sW1[0][k1] + xv * sW1[1][k1] + sW1[2][k1], 0.f);
        double pa = pack2(a2v.x), pb = pack2(a2v.y);
        double ph = pack2(h1a),   pi = pack2(h1b);
        const double2* wl0 = (const double2*)(sWl + k0 * HIDC);
        const double2* wl1 = (const double2*)(sWl + k1 * HIDC);
        const double2* wr0 = (const double2*)(sWr + k0 * HIDC);
        const double2* wr1 = (const double2*)(sWr + k1 * HIDC);
#pragma unroll
        for (int jb = 0; jb < 16; jb++) {
            double2 w0 = wl0[jb], w1 = wl1[jb], u0 = wr0[jb], u1 = wr1[jb];
            FMA2(acc2[2 * jb],     pa, w0.x); FMA2(acc2[2 * jb + 1], pa, w0.y);
            FMA2(acc2[2 * jb],     pb, w1.x); FMA2(acc2[2 * jb + 1], pb, w1.y);
            FMA2(acc2[2 * jb],     ph, u0.x); FMA2(acc2[2 * jb + 1], ph, u0.y);
            FMA2(acc2[2 * jb],     pi, u1.x); FMA2(acc2[2 * jb + 1], pi, u1.y);
        }
    }

    bool uni = __all_sync(0xffffffffu, g == __shfl_sync(0xffffffffu, g, 0));
    float* pooledf = (float*)g_pooled;
#pragma unroll
    for (int jb = 0; jb < 16; jb++) {
        double p0 = acc2[2 * jb], p1 = acc2[2 * jb + 1];
        float4 v;
        v.x = fmaxf(__int_as_float(__double2loint(p0)), 0.f);
        v.y = fmaxf(__int_as_float(__double2hiint(p0)), 0.f);
        v.z = fmaxf(__int_as_float(__double2loint(p1)), 0.f);
        v.w = fmaxf(__int_as_float(__double2hiint(p1)), 0.f);
        if (uni) {
            for (int o = 16; o > 0; o >>= 1) {
                v.x += __shfl_xor_sync(0xffffffffu, v.x, o);
                v.y += __shfl_xor_sync(0xffffffffu, v.y, o);
                v.z += __shfl_xor_sync(0xffffffffu, v.z, o);
                v.w += __shfl_xor_sync(0xffffffffu, v.w, o);
            }
            if ((tid & 31) == 0)
                atomicAdd((float4*)(pooledf + g * HIDC + 4 * jb), v);
        } else {
            atomicAdd((float4*)(pooledf + g * HIDC + 4 * jb), v);
        }
    }
}

// ---------------- classifier ----------------
__global__ void k_cls(const float* __restrict__ Wc, const float* __restrict__ bc,
                      float* __restrict__ out) {
    __shared__ float sp[HIDC];
    int g = blockIdx.x, t = threadIdx.x;   // 32 threads
    float invg = 1.0f / fmaxf(g_gcnt[g], 1.0f);
    const float* pooledf = (const float*)g_pooled;
    sp[t] = pooledf[g * HIDC + t] * invg;
    sp[t + 32] = pooledf[g * HIDC + 32 + t] * invg;
    __syncwarp();
    if (t < NCLS) {
        float a = __ldg(&bc[t]);
#pragma unroll
        for (int j = 0; j < HIDC; j++) a += sp[j] * __ldg(&Wc[j * NCLS + t]);
        out[g * NCLS + t] = a;
    }
}

// ---------------- launch ----------------
extern "C" void kernel_launch(void* const* d_in, const int* in_sizes, int n_in,
                              void* d_out, int out_size) {
    const float* x   = (const float*)d_in[0];
    const void*  ei  = d_in[1];
    const void*  bt  = d_in[2];
    const float* W1l = (const float*)d_in[3];
    const float* b1  = (const float*)d_in[4];
    const float* W1r = (const float*)d_in[5];
    const float* W2l = (const float*)d_in[6];
    const float* b2  = (const float*)d_in[7];
    const float* W2r = (const float*)d_in[8];
    const float* Wc  = (const float*)d_in[9];
    const float* bc  = (const float*)d_in[10];
    float* out = (float*)d_out;

    k_zero<<<512, 256>>>((const int*)ei, (const int*)bt);
    k_hist<<<N_EDGESC / 1024, 256>>>(ei);
    k_scan<<<SCAN_BLKS, 256>>>();
    k_scatter<<<N_EDGESC / 512, 256>>>(ei, x);
    k_s1<<<(N_NODESC + 255) / 256, 256>>>(x, bt);
    k_sweep2<<<N_NODESC / 8, 256>>>(W1l, b1, W1r);
    k_h2pool<<<N_NODESC / 160, 160>>>(bt, W1l, b1, W1r, W2l, b2, W2r);
    k_cls<<<N_GRAPHSC, 32>>>(Wc, bc, out);
}